// round 2
// baseline (speedup 1.0000x reference)
#include <cuda_runtime.h>

// B=65536 poses, N=128 keypoints. out layout (B, 2, N) fp32.
// Block = 256 threads = 8 warps = 8 poses. Warp w handles pose blockIdx.x*8+w,
// lane l handles keypoints 4l..4l+3.
//
// Phase 1: threads 0-7 compute the folded projection matrix
//   M = diag(1/640,1/480,1) * K * R(quat),  tc = diag(..) * K * [0,0,0.7]
// and write it to smem as DUPLICATED pairs (m,m) so phase 2 gets ready-made
// f32x2 packed operands from plain LDS.128.
// Phase 2: packed f32x2 math, 2 keypoints per instruction.

__device__ __forceinline__ unsigned long long ffma2(unsigned long long a,
                                                    unsigned long long b,
                                                    unsigned long long c) {
    unsigned long long d;
    asm("fma.rn.f32x2 %0, %1, %2, %3;" : "=l"(d) : "l"(a), "l"(b), "l"(c));
    return d;
}

__device__ __forceinline__ unsigned long long fmul2(unsigned long long a,
                                                    unsigned long long b) {
    unsigned long long d;
    asm("mul.rn.f32x2 %0, %1, %2;" : "=l"(d) : "l"(a), "l"(b));
    return d;
}

__device__ __forceinline__ float frcp_fast(float a) {
    float r;
    asm("rcp.approx.f32 %0, %1;" : "=f"(r) : "f"(a));
    return r;
}

union P2 {
    unsigned long long u;
    float2 f;
};

__device__ __forceinline__ unsigned long long pack2(float lo, float hi) {
    P2 p; p.f = make_float2(lo, hi); return p.u;
}

__global__ __launch_bounds__(256) void pose_kernel(
    const float4* __restrict__ quat,      // B x 4
    const float*  __restrict__ kp,        // 3 x 128
    const float*  __restrict__ cam,       // 3 x 3
    float4*       __restrict__ out)       // B * 64 float4
{
    // 8 poses x 12 packed pairs (24 floats) each; 16B-aligned rows (96 B).
    __shared__ __align__(16) float sM[8][24];

    const int tid  = threadIdx.x;
    const int warp = tid >> 5;
    const int lane = tid & 31;

    // ---- Phase 1: threads 0..7 compute folded matrix for pose 'tid' ----
    if (tid < 8) {
        const int b = blockIdx.x * 8 + tid;
        float4 q = quat[b];
        const float x = q.x, y = q.y, z = q.z, w = q.w;

        const float xx = x * x, yy = y * y, zz = z * z;
        const float xy = x * y, xz = x * z, yz = y * z;
        const float xw = x * w, yw = y * w, zw = z * w;
        const float r00 = 1.0f - 2.0f * (yy + zz), r01 = 2.0f * (xy - zw), r02 = 2.0f * (xz + yw);
        const float r10 = 2.0f * (xy + zw), r11 = 1.0f - 2.0f * (xx + zz), r12 = 2.0f * (yz - xw);
        const float r20 = 2.0f * (xz - yw), r21 = 2.0f * (yz + xw), r22 = 1.0f - 2.0f * (xx + yy);

        const float k00 = cam[0], k01 = cam[1], k02 = cam[2];
        const float k10 = cam[3], k11 = cam[4], k12 = cam[5];
        const float k20 = cam[6], k21 = cam[7], k22 = cam[8];

        const float su = 1.0f / 640.0f, sv = 1.0f / 480.0f;

        const float m00 = su * (k00 * r00 + k01 * r10 + k02 * r20);
        const float m01 = su * (k00 * r01 + k01 * r11 + k02 * r21);
        const float m02 = su * (k00 * r02 + k01 * r12 + k02 * r22);
        const float m10 = sv * (k10 * r00 + k11 * r10 + k12 * r20);
        const float m11 = sv * (k10 * r01 + k11 * r11 + k12 * r21);
        const float m12 = sv * (k10 * r02 + k11 * r12 + k12 * r22);
        const float m20 = k20 * r00 + k21 * r10 + k22 * r20;
        const float m21 = k20 * r01 + k21 * r11 + k22 * r21;
        const float m22 = k20 * r02 + k21 * r12 + k22 * r22;
        const float t0 = su * (k02 * 0.7f);
        const float t1 = sv * (k12 * 0.7f);
        const float t2 = k22 * 0.7f;

        float2* sp = reinterpret_cast<float2*>(sM[tid]);
        sp[0]  = make_float2(m00, m00);
        sp[1]  = make_float2(m01, m01);
        sp[2]  = make_float2(m02, m02);
        sp[3]  = make_float2(t0,  t0);
        sp[4]  = make_float2(m10, m10);
        sp[5]  = make_float2(m11, m11);
        sp[6]  = make_float2(m12, m12);
        sp[7]  = make_float2(t1,  t1);
        sp[8]  = make_float2(m20, m20);
        sp[9]  = make_float2(m21, m21);
        sp[10] = make_float2(m22, m22);
        sp[11] = make_float2(t2,  t2);
    }
    __syncthreads();

    // ---- Phase 2: packed per-point math ----
    // 12 packed operands via 6 broadcast LDS.128
    const ulonglong2* Mv = reinterpret_cast<const ulonglong2*>(sM[warp]);
    ulonglong2 v0 = Mv[0];   // (m00,m00), (m01,m01)
    ulonglong2 v1 = Mv[1];   // (m02,m02), (t0,t0)
    ulonglong2 v2 = Mv[2];   // (m10,m10), (m11,m11)
    ulonglong2 v3 = Mv[3];   // (m12,m12), (t1,t1)
    ulonglong2 v4 = Mv[4];   // (m20,m20), (m21,m21)
    ulonglong2 v5 = Mv[5];   // (m22,m22), (t2,t2)

    const unsigned long long M00 = v0.x, M01 = v0.y, M02 = v1.x, T0 = v1.y;
    const unsigned long long M10 = v2.x, M11 = v2.y, M12 = v3.x, T1 = v3.y;
    const unsigned long long M20 = v4.x, M21 = v4.y, M22 = v5.x, T2 = v5.y;

    // keypoints as packed pairs: each LDG.128 gives two f32x2 operands
    const ulonglong2 PX = reinterpret_cast<const ulonglong2*>(kp)[lane];
    const ulonglong2 PY = reinterpret_cast<const ulonglong2*>(kp + 128)[lane];
    const ulonglong2 PZ = reinterpret_cast<const ulonglong2*>(kp + 256)[lane];

    // pair 0: points 4l, 4l+1
    unsigned long long i0a = ffma2(M00, PX.x, ffma2(M01, PY.x, ffma2(M02, PZ.x, T0)));
    unsigned long long i1a = ffma2(M10, PX.x, ffma2(M11, PY.x, ffma2(M12, PZ.x, T1)));
    unsigned long long i2a = ffma2(M20, PX.x, ffma2(M21, PY.x, ffma2(M22, PZ.x, T2)));
    // pair 1: points 4l+2, 4l+3
    unsigned long long i0b = ffma2(M00, PX.y, ffma2(M01, PY.y, ffma2(M02, PZ.y, T0)));
    unsigned long long i1b = ffma2(M10, PX.y, ffma2(M11, PY.y, ffma2(M12, PZ.y, T1)));
    unsigned long long i2b = ffma2(M20, PX.y, ffma2(M21, PY.y, ffma2(M22, PZ.y, T2)));

    P2 za; za.u = i2a;
    P2 zb; zb.u = i2b;
    const unsigned long long RZa = pack2(frcp_fast(za.f.x), frcp_fast(za.f.y));
    const unsigned long long RZb = pack2(frcp_fast(zb.f.x), frcp_fast(zb.f.y));

    P2 ua; ua.u = fmul2(i0a, RZa);
    P2 ub; ub.u = fmul2(i0b, RZb);
    P2 va; va.u = fmul2(i1a, RZa);
    P2 vb; vb.u = fmul2(i1b, RZb);

    const int base = (blockIdx.x * 8 + warp) * 64;
    out[base + lane]      = make_float4(ua.f.x, ua.f.y, ub.f.x, ub.f.y);
    out[base + 32 + lane] = make_float4(va.f.x, va.f.y, vb.f.x, vb.f.y);
}

extern "C" void kernel_launch(void* const* d_in, const int* in_sizes, int n_in,
                              void* d_out, int out_size)
{
    const float4* quat = (const float4*)d_in[0];
    const float*  kp   = (const float*)d_in[1];
    const float*  cam  = (const float*)d_in[2];
    float4* out = (float4*)d_out;

    const int B = in_sizes[0] / 4;          // 65536
    const int blocks = B / 8;               // 8 poses per 256-thread block
    pose_kernel<<<blocks, 256>>>(quat, kp, cam, out);
}